// round 11
// baseline (speedup 1.0000x reference)
#include <cuda_runtime.h>
#include <cuda_bf16.h>
#include <cstdint>
#include <cstddef>

#define NSTEP 32768
#define HH 128
#define G3 384
#define KDIM 530
#define EDIM 512
#define ADIM 18
#define FCDIM 256

__device__ float g_gi_pred[(size_t)NSTEP * G3];
__device__ float g_gi_true[(size_t)NSTEP * G3];
__device__ float g_hpred[(size_t)NSTEP * HH];

typedef unsigned long long ull;

__device__ __forceinline__ ull ffma2(ull a, ull b, ull c) {
    ull d;
    asm("fma.rn.f32x2 %0, %1, %2, %3;" : "=l"(d) : "l"(a), "l"(b), "l"(c));
    return d;
}
__device__ __forceinline__ float plo(ull a) { return __uint_as_float((unsigned)a); }
__device__ __forceinline__ float phi(ull a) { return __uint_as_float((unsigned)(a >> 32)); }

__device__ __forceinline__ float tanh_a(float x) {
    float y;
    asm("tanh.approx.f32 %0, %1;" : "=f"(y) : "f"(x));
    return y;
}
__device__ __forceinline__ float sig_a(float x) {
    return fmaf(0.5f, tanh_a(0.5f * x), 0.5f);
}
__device__ __forceinline__ float sigf(float x) {
    return __fdividef(1.f, 1.f + __expf(-x));
}
__device__ __forceinline__ void cpa16(unsigned dst, const void* src) {
    asm volatile("cp.async.cg.shared.global [%0], [%1], 16;" :: "r"(dst), "l"(src));
}

// ============================================================================
// Kernel 1: gi = concat(enc, act) @ Wih.T + bih  (unchanged, proven)
// ============================================================================
__global__ void __launch_bounds__(256) gi_gemm(
    const float* __restrict__ encp, const float* __restrict__ enct,
    const float* __restrict__ act,  const float* __restrict__ Wih,
    const float* __restrict__ bih)
{
    const float* A = blockIdx.z ? enct : encp;
    float* C = blockIdx.z ? g_gi_true : g_gi_pred;

    __shared__ __align__(16) float As[16][68];
    __shared__ __align__(16) float Bs[16][68];

    int t = threadIdx.x;
    int m0 = blockIdx.x * 64, n0 = blockIdx.y * 64;
    int tx = t & 15, ty = t >> 4;
    int arow = t >> 2, ac4 = (t & 3) * 4;

    float acc[4][4];
#pragma unroll
    for (int a = 0; a < 4; a++)
#pragma unroll
        for (int b = 0; b < 4; b++) acc[a][b] = 0.f;

    for (int kt = 0; kt < 34; kt++) {
        int k0 = kt * 16;
        float av[4], bv[4];
        if (k0 < EDIM) {
            float4 v = *(const float4*)(A + (size_t)(m0 + arow) * EDIM + k0 + ac4);
            av[0] = v.x; av[1] = v.y; av[2] = v.z; av[3] = v.w;
            const float* bp = Wih + (size_t)(n0 + arow) * KDIM + k0 + ac4;
            float2 u0 = *(const float2*)(bp);
            float2 u1 = *(const float2*)(bp + 2);
            bv[0] = u0.x; bv[1] = u0.y; bv[2] = u1.x; bv[3] = u1.y;
        } else {
#pragma unroll
            for (int j = 0; j < 4; j++) {
                int kg = k0 + ac4 + j;
                av[j] = (kg < KDIM) ? act[(size_t)(m0 + arow) * ADIM + (kg - EDIM)] : 0.f;
                bv[j] = (kg < KDIM) ? Wih[(size_t)(n0 + arow) * KDIM + kg] : 0.f;
            }
        }
        __syncthreads();
#pragma unroll
        for (int j = 0; j < 4; j++) { As[ac4 + j][arow] = av[j]; Bs[ac4 + j][arow] = bv[j]; }
        __syncthreads();
#pragma unroll
        for (int kk = 0; kk < 16; kk++) {
            float4 a4 = *(const float4*)&As[kk][ty * 4];
            float4 b4 = *(const float4*)&Bs[kk][tx * 4];
            float ar[4] = {a4.x, a4.y, a4.z, a4.w};
            float br[4] = {b4.x, b4.y, b4.z, b4.w};
#pragma unroll
            for (int r = 0; r < 4; r++)
#pragma unroll
                for (int cc = 0; cc < 4; cc++) acc[r][cc] += ar[r] * br[cc];
        }
    }
#pragma unroll
    for (int r = 0; r < 4; r++) {
        int m = m0 + ty * 4 + r;
#pragma unroll
        for (int cc = 0; cc < 4; cc++) {
            int n = n0 + tx * 4 + cc;
            C[(size_t)m * G3 + n] = acc[r][cc] + bih[n];
        }
    }
}

// ============================================================================
// Kernel 2: GRU scan — best-known architecture (R10) + activation micro-folds.
// 256 thr, two-lane split, FFMA2 matvec, 1 shfl, 1 bar/step, 16B ring.
// ============================================================================
__global__ void __launch_bounds__(256, 1) gru_scan(
    const float* __restrict__ Whh, const float* __restrict__ bhh,
    const float* __restrict__ h0)
{
    __shared__ __align__(16) float ring[4][768];   // [pred 384 | true 384] per slot
    __shared__ __align__(16) float hbuf[2][HH];

    int t = threadIdx.x;
    int i = t >> 1;
    int c = t & 1;

    // Register-resident weights: 3 gates x 64 contiguous columns = 96 ull
    ull wr[32], wz[32], wn[32];
    {
        const ull* pr = (const ull*)(Whh + (size_t)i * HH + c * 64);
        const ull* pz = (const ull*)(Whh + (size_t)(HH + i) * HH + c * 64);
        const ull* pn = (const ull*)(Whh + (size_t)(2 * HH + i) * HH + c * 64);
#pragma unroll
        for (int q = 0; q < 32; q++) { wr[q] = pr[q]; wz[q] = pz[q]; wn[q] = pn[q]; }
    }
    float br = bhh[i], bz = bhh[HH + i], bn = bhh[2 * HH + i];
    if (t < HH) hbuf[0][t] = h0[t];

    // ---- Ring prefill: slots 0,1,2 (16B cp.async, threads 0..191) ----
#pragma unroll
    for (int k = 0; k < 3; k++) {
        unsigned dst = (unsigned)__cvta_generic_to_shared(&ring[k][0]);
        if (t < 96) cpa16(dst + t * 16, (const char*)(g_gi_pred + (size_t)k * G3) + t * 16);
        else if (t < 192) cpa16(dst + 1536 + (t - 96) * 16,
                                (const char*)(g_gi_true + (size_t)k * G3) + (t - 96) * 16);
        asm volatile("cp.async.commit_group;");
    }
    asm volatile("cp.async.wait_group 2;" ::: "memory");
    __syncthreads();

    for (int s = 0; s < NSTEP; s++) {
        // ---- issue prefetch for slot s+3 ----
        if (s + 3 < NSTEP) {
            unsigned dst = (unsigned)__cvta_generic_to_shared(&ring[(s + 3) & 3][0]);
            if (t < 96) cpa16(dst + t * 16, (const char*)(g_gi_pred + (size_t)(s + 3) * G3) + t * 16);
            else if (t < 192) cpa16(dst + 1536 + (t - 96) * 16,
                                    (const char*)(g_gi_true + (size_t)(s + 3) * G3) + (t - 96) * 16);
        }
        asm volatile("cp.async.commit_group;");

        // ---- ring loads for this step (latency hidden under matvec) ----
        const float* gb = &ring[s & 3][c * 384];
        float g0 = gb[i], g1 = gb[HH + i], g2 = gb[2 * HH + i];

        // ---- matvec: gh partial over this thread's 64 columns ----
        const ulonglong2* hp2 = (const ulonglong2*)(hbuf[s & 1] + c * 64);
        ull ar = 0, az = 0, an = 0;
#pragma unroll
        for (int q = 0; q < 16; q++) {
            ulonglong2 hq = hp2[q];
            ar = ffma2(wr[2 * q],     hq.x, ar);
            az = ffma2(wz[2 * q],     hq.x, az);
            an = ffma2(wn[2 * q],     hq.x, an);
            ar = ffma2(wr[2 * q + 1], hq.y, ar);
            az = ffma2(wz[2 * q + 1], hq.y, az);
            an = ffma2(wn[2 * q + 1], hq.y, an);
        }
        float sr = plo(ar) + phi(ar);
        float sz = plo(az) + phi(az);
        float sn = plo(an) + phi(an);
        sr += __shfl_xor_sync(0xffffffffu, sr, 1);
        sz += __shfl_xor_sync(0xffffffffu, sz, 1);
        sn += __shfl_xor_sync(0xffffffffu, sn, 1);

        // ---- symmetric GRU update (c==0: pred->out, c==1: true->state) ----
        // r*ghn folded: r = 0.5*tanh(0.5*xr)+0.5  =>  r*ghn = tanh(0.5*xr)*hghn + hghn
        float hprev = hbuf[s & 1][i];
        float hghn = 0.5f * (sn + bn);
        float tr = tanh_a(0.5f * (g0 + sr + br));
        float z  = sig_a(g1 + sz + bz);
        float n  = tanh_a(g2 + fmaf(tr, hghn, hghn));
        float hnew = fmaf(z, hprev - n, n);
        if (c) hbuf[(s + 1) & 1][i] = hnew;
        else   g_hpred[(size_t)s * HH + i] = hnew;

        asm volatile("cp.async.wait_group 2;" ::: "memory");
        __syncthreads();
    }
}

// ============================================================================
// Kernel 3: MLP head (unchanged, proven)
// ============================================================================
__global__ void __launch_bounds__(256) mlp_head(
    const float* __restrict__ fc1w, const float* __restrict__ fc1b,
    const float* __restrict__ fc2w, const float* __restrict__ fc2b,
    float* __restrict__ out)
{
    extern __shared__ float sm[];
    float* w1  = sm;
    float* b1  = sm + FCDIM * HH;
    float* w2  = b1 + FCDIM;
    float* hs  = w2 + FCDIM;
    float* red = hs + HH;

    int t = threadIdx.x;
    for (int idx = t; idx < FCDIM * HH; idx += 256) w1[idx] = fc1w[idx];
    b1[t] = fc1b[t];
    w2[t] = fc2w[t];
    __syncthreads();

    float myb = b1[t], myw2 = w2[t];
    const float4* wj = (const float4*)(w1 + t * HH);

    for (int r = 0; r < 64; r++) {
        size_t row = (size_t)blockIdx.x * 64 + r;
        if (t < HH) hs[t] = g_hpred[row * HH + t];
        __syncthreads();
        float acc = 0.f;
        const float4* hv = (const float4*)hs;
#pragma unroll
        for (int q = 0; q < 32; q++) {
            float4 a = wj[q], b = hv[q];
            acc += a.x * b.x; acc += a.y * b.y; acc += a.z * b.z; acc += a.w * b.w;
        }
        float v = acc + myb;
        v = v > 0.f ? v : 0.f;
        v *= myw2;
#pragma unroll
        for (int m = 16; m; m >>= 1) v += __shfl_xor_sync(0xffffffffu, v, m);
        if ((t & 31) == 0) red[t >> 5] = v;
        __syncthreads();
        if (t == 0) {
            float sv = red[0] + red[1] + red[2] + red[3] +
                       red[4] + red[5] + red[6] + red[7] + fc2b[0];
            out[row] = sigf(sv);
        }
        __syncthreads();
    }
}

// ncu (-s 5 -c 1) empirically captures the 4th launch: pad so gru_scan is 4th.
__global__ void probe_pad() {}

extern "C" void kernel_launch(void* const* d_in, const int* in_sizes, int n_in,
                              void* d_out, int out_size) {
    const float* enc  = (const float*)d_in[0];
    const float* act  = (const float*)d_in[1];
    const float* tru  = (const float*)d_in[2];
    const float* Wih  = (const float*)d_in[3];
    const float* Whh  = (const float*)d_in[4];
    const float* bih  = (const float*)d_in[5];
    const float* bhh  = (const float*)d_in[6];
    const float* h0   = (const float*)d_in[7];
    const float* fc1w = (const float*)d_in[8];
    const float* fc1b = (const float*)d_in[9];
    const float* fc2w = (const float*)d_in[10];
    const float* fc2b = (const float*)d_in[11];
    float* out = (float*)d_out;

    int mlp_smem = (FCDIM * HH + FCDIM + FCDIM + HH + 8) * 4;
    cudaFuncSetAttribute(mlp_head, cudaFuncAttributeMaxDynamicSharedMemorySize, mlp_smem);

    dim3 g(512, 6, 2);
    gi_gemm<<<g, 256>>>(enc, tru, act, Wih, bih);
    probe_pad<<<1, 1>>>();
    probe_pad<<<1, 1>>>();
    gru_scan<<<1, 256>>>(Whh, bhh, h0);    // 4th launch -> ncu capture window
    mlp_head<<<512, 256, mlp_smem>>>(fc1w, fc1b, fc2w, fc2b, out);
}

// round 13
// speedup vs baseline: 1.0259x; 1.0259x over previous
#include <cuda_runtime.h>
#include <cuda_bf16.h>
#include <cstdint>
#include <cstddef>

#define NSTEP 32768
#define HH 128
#define G3 384
#define KDIM 530
#define EDIM 512
#define ADIM 18
#define FCDIM 256

__device__ float g_gi_pred[(size_t)NSTEP * G3];
__device__ float g_gi_true[(size_t)NSTEP * G3];
__device__ float g_hpred[(size_t)NSTEP * HH];

typedef unsigned long long ull;

__device__ __forceinline__ ull ffma2(ull a, ull b, ull c) {
    ull d;
    asm("fma.rn.f32x2 %0, %1, %2, %3;" : "=l"(d) : "l"(a), "l"(b), "l"(c));
    return d;
}
__device__ __forceinline__ float plo(ull a) { return __uint_as_float((unsigned)a); }
__device__ __forceinline__ float phi(ull a) { return __uint_as_float((unsigned)(a >> 32)); }

__device__ __forceinline__ float tanh_a(float x) {
    float y;
    asm("tanh.approx.f32 %0, %1;" : "=f"(y) : "f"(x));
    return y;
}
__device__ __forceinline__ float sig_a(float x) {
    return fmaf(0.5f, tanh_a(0.5f * x), 0.5f);
}
__device__ __forceinline__ float sigf(float x) {
    return __fdividef(1.f, 1.f + __expf(-x));
}
__device__ __forceinline__ void cpa16(unsigned dst, const void* src) {
    asm volatile("cp.async.cg.shared.global [%0], [%1], 16;" :: "r"(dst), "l"(src));
}

// ============================================================================
// Kernel 1: gi = concat(enc, act) @ Wih.T + bih  (unchanged, proven)
// ============================================================================
__global__ void __launch_bounds__(256) gi_gemm(
    const float* __restrict__ encp, const float* __restrict__ enct,
    const float* __restrict__ act,  const float* __restrict__ Wih,
    const float* __restrict__ bih)
{
    const float* A = blockIdx.z ? enct : encp;
    float* C = blockIdx.z ? g_gi_true : g_gi_pred;

    __shared__ __align__(16) float As[16][68];
    __shared__ __align__(16) float Bs[16][68];

    int t = threadIdx.x;
    int m0 = blockIdx.x * 64, n0 = blockIdx.y * 64;
    int tx = t & 15, ty = t >> 4;
    int arow = t >> 2, ac4 = (t & 3) * 4;

    float acc[4][4];
#pragma unroll
    for (int a = 0; a < 4; a++)
#pragma unroll
        for (int b = 0; b < 4; b++) acc[a][b] = 0.f;

    for (int kt = 0; kt < 34; kt++) {
        int k0 = kt * 16;
        float av[4], bv[4];
        if (k0 < EDIM) {
            float4 v = *(const float4*)(A + (size_t)(m0 + arow) * EDIM + k0 + ac4);
            av[0] = v.x; av[1] = v.y; av[2] = v.z; av[3] = v.w;
            const float* bp = Wih + (size_t)(n0 + arow) * KDIM + k0 + ac4;
            float2 u0 = *(const float2*)(bp);
            float2 u1 = *(const float2*)(bp + 2);
            bv[0] = u0.x; bv[1] = u0.y; bv[2] = u1.x; bv[3] = u1.y;
        } else {
#pragma unroll
            for (int j = 0; j < 4; j++) {
                int kg = k0 + ac4 + j;
                av[j] = (kg < KDIM) ? act[(size_t)(m0 + arow) * ADIM + (kg - EDIM)] : 0.f;
                bv[j] = (kg < KDIM) ? Wih[(size_t)(n0 + arow) * KDIM + kg] : 0.f;
            }
        }
        __syncthreads();
#pragma unroll
        for (int j = 0; j < 4; j++) { As[ac4 + j][arow] = av[j]; Bs[ac4 + j][arow] = bv[j]; }
        __syncthreads();
#pragma unroll
        for (int kk = 0; kk < 16; kk++) {
            float4 a4 = *(const float4*)&As[kk][ty * 4];
            float4 b4 = *(const float4*)&Bs[kk][tx * 4];
            float ar[4] = {a4.x, a4.y, a4.z, a4.w};
            float br[4] = {b4.x, b4.y, b4.z, b4.w};
#pragma unroll
            for (int r = 0; r < 4; r++)
#pragma unroll
                for (int cc = 0; cc < 4; cc++) acc[r][cc] += ar[r] * br[cc];
        }
    }
#pragma unroll
    for (int r = 0; r < 4; r++) {
        int m = m0 + ty * 4 + r;
#pragma unroll
        for (int cc = 0; cc < 4; cc++) {
            int n = n0 + tx * 4 + cc;
            C[(size_t)m * G3 + n] = acc[r][cc] + bih[n];
        }
    }
}

// ============================================================================
// Kernel 2: GRU scan — R10 champion architecture, exact revert.
// 256 thr, two-lane split, FFMA2 matvec, 1 shfl level, 1 bar/step, 16B ring.
// Only change vs R10: shfl order sr, sn, sz (critical chain sr->r->n).
// ============================================================================
__global__ void __launch_bounds__(256, 1) gru_scan(
    const float* __restrict__ Whh, const float* __restrict__ bhh,
    const float* __restrict__ h0)
{
    __shared__ __align__(16) float ring[4][768];   // [pred 384 | true 384] per slot
    __shared__ __align__(16) float hbuf[2][HH];

    int t = threadIdx.x;
    int i = t >> 1;
    int c = t & 1;

    // Register-resident weights: 3 gates x 64 contiguous columns = 96 ull
    ull wr[32], wz[32], wn[32];
    {
        const ull* pr = (const ull*)(Whh + (size_t)i * HH + c * 64);
        const ull* pz = (const ull*)(Whh + (size_t)(HH + i) * HH + c * 64);
        const ull* pn = (const ull*)(Whh + (size_t)(2 * HH + i) * HH + c * 64);
#pragma unroll
        for (int q = 0; q < 32; q++) { wr[q] = pr[q]; wz[q] = pz[q]; wn[q] = pn[q]; }
    }
    float br = bhh[i], bz = bhh[HH + i], bn = bhh[2 * HH + i];
    if (t < HH) hbuf[0][t] = h0[t];

    // ---- Ring prefill: slots 0,1,2 (16B cp.async, threads 0..191) ----
#pragma unroll
    for (int k = 0; k < 3; k++) {
        unsigned dst = (unsigned)__cvta_generic_to_shared(&ring[k][0]);
        if (t < 96) cpa16(dst + t * 16, (const char*)(g_gi_pred + (size_t)k * G3) + t * 16);
        else if (t < 192) cpa16(dst + 1536 + (t - 96) * 16,
                                (const char*)(g_gi_true + (size_t)k * G3) + (t - 96) * 16);
        asm volatile("cp.async.commit_group;");
    }
    asm volatile("cp.async.wait_group 2;" ::: "memory");
    __syncthreads();

    for (int s = 0; s < NSTEP; s++) {
        // ---- issue prefetch for slot s+3 ----
        if (s + 3 < NSTEP) {
            unsigned dst = (unsigned)__cvta_generic_to_shared(&ring[(s + 3) & 3][0]);
            if (t < 96) cpa16(dst + t * 16, (const char*)(g_gi_pred + (size_t)(s + 3) * G3) + t * 16);
            else if (t < 192) cpa16(dst + 1536 + (t - 96) * 16,
                                    (const char*)(g_gi_true + (size_t)(s + 3) * G3) + (t - 96) * 16);
        }
        asm volatile("cp.async.commit_group;");

        // ---- ring loads for this step (latency hidden under matvec) ----
        const float* gb = &ring[s & 3][c * 384];
        float g0 = gb[i], g1 = gb[HH + i], g2 = gb[2 * HH + i];

        // ---- matvec: gh partial over this thread's 64 columns ----
        const ulonglong2* hp2 = (const ulonglong2*)(hbuf[s & 1] + c * 64);
        ull ar = 0, az = 0, an = 0;
#pragma unroll
        for (int q = 0; q < 16; q++) {
            ulonglong2 hq = hp2[q];
            ar = ffma2(wr[2 * q],     hq.x, ar);
            az = ffma2(wz[2 * q],     hq.x, az);
            an = ffma2(wn[2 * q],     hq.x, an);
            ar = ffma2(wr[2 * q + 1], hq.y, ar);
            az = ffma2(wz[2 * q + 1], hq.y, az);
            an = ffma2(wn[2 * q + 1], hq.y, an);
        }
        float sr = plo(ar) + phi(ar);
        float sn = plo(an) + phi(an);
        float sz = plo(az) + phi(az);
        sr += __shfl_xor_sync(0xffffffffu, sr, 1);
        sn += __shfl_xor_sync(0xffffffffu, sn, 1);
        sz += __shfl_xor_sync(0xffffffffu, sz, 1);

        // ---- symmetric GRU update (c==0: pred->out, c==1: true->state) ----
        float hprev = hbuf[s & 1][i];
        float r = sig_a(g0 + sr + br);
        float z = sig_a(g1 + sz + bz);
        float n = tanh_a(g2 + r * (sn + bn));
        float hnew = (1.f - z) * n + z * hprev;
        if (c) hbuf[(s + 1) & 1][i] = hnew;
        else   g_hpred[(size_t)s * HH + i] = hnew;

        asm volatile("cp.async.wait_group 2;" ::: "memory");
        __syncthreads();
    }
}

// ============================================================================
// Kernel 3: MLP head (unchanged, proven)
// ============================================================================
__global__ void __launch_bounds__(256) mlp_head(
    const float* __restrict__ fc1w, const float* __restrict__ fc1b,
    const float* __restrict__ fc2w, const float* __restrict__ fc2b,
    float* __restrict__ out)
{
    extern __shared__ float sm[];
    float* w1  = sm;
    float* b1  = sm + FCDIM * HH;
    float* w2  = b1 + FCDIM;
    float* hs  = w2 + FCDIM;
    float* red = hs + HH;

    int t = threadIdx.x;
    for (int idx = t; idx < FCDIM * HH; idx += 256) w1[idx] = fc1w[idx];
    b1[t] = fc1b[t];
    w2[t] = fc2w[t];
    __syncthreads();

    float myb = b1[t], myw2 = w2[t];
    const float4* wj = (const float4*)(w1 + t * HH);

    for (int r = 0; r < 64; r++) {
        size_t row = (size_t)blockIdx.x * 64 + r;
        if (t < HH) hs[t] = g_hpred[row * HH + t];
        __syncthreads();
        float acc = 0.f;
        const float4* hv = (const float4*)hs;
#pragma unroll
        for (int q = 0; q < 32; q++) {
            float4 a = wj[q], b = hv[q];
            acc += a.x * b.x; acc += a.y * b.y; acc += a.z * b.z; acc += a.w * b.w;
        }
        float v = acc + myb;
        v = v > 0.f ? v : 0.f;
        v *= myw2;
#pragma unroll
        for (int m = 16; m; m >>= 1) v += __shfl_xor_sync(0xffffffffu, v, m);
        if ((t & 31) == 0) red[t >> 5] = v;
        __syncthreads();
        if (t == 0) {
            float sv = red[0] + red[1] + red[2] + red[3] +
                       red[4] + red[5] + red[6] + red[7] + fc2b[0];
            out[row] = sigf(sv);
        }
        __syncthreads();
    }
}

extern "C" void kernel_launch(void* const* d_in, const int* in_sizes, int n_in,
                              void* d_out, int out_size) {
    const float* enc  = (const float*)d_in[0];
    const float* act  = (const float*)d_in[1];
    const float* tru  = (const float*)d_in[2];
    const float* Wih  = (const float*)d_in[3];
    const float* Whh  = (const float*)d_in[4];
    const float* bih  = (const float*)d_in[5];
    const float* bhh  = (const float*)d_in[6];
    const float* h0   = (const float*)d_in[7];
    const float* fc1w = (const float*)d_in[8];
    const float* fc1b = (const float*)d_in[9];
    const float* fc2w = (const float*)d_in[10];
    const float* fc2b = (const float*)d_in[11];
    float* out = (float*)d_out;

    int mlp_smem = (FCDIM * HH + FCDIM + FCDIM + HH + 8) * 4;
    cudaFuncSetAttribute(mlp_head, cudaFuncAttributeMaxDynamicSharedMemorySize, mlp_smem);

    dim3 g(512, 6, 2);
    gi_gemm<<<g, 256>>>(enc, tru, act, Wih, bih);
    gru_scan<<<1, 256>>>(Whh, bhh, h0);
    mlp_head<<<512, 256, mlp_smem>>>(fc1w, fc1b, fc2w, fc2b, out);
}